// round 14
// baseline (speedup 1.0000x reference)
#include <cuda_runtime.h>
#include <cuda_fp16.h>
#include <cstdint>

#define EMBED 1024
#define NHEAD 16
#define HDIM  64
#define TLEN  1024
#define BSZ   4
#define MROWS (TLEN*BSZ)          // 4096
#define SCALE 0.03125f            // 1/sqrt(1024)

// Scratch (device globals; no allocation allowed)
__device__ __half g_q[(size_t)MROWS * EMBED];
__device__ __half g_k[(size_t)MROWS * EMBED];
__device__ __half g_v[(size_t)MROWS * EMBED];
__device__ __half g_o[(size_t)MROWS * EMBED];
__device__ __half g_hx[(size_t)3 * MROWS * EMBED];     // half(query|key|value)
__device__ __half g_hwi[(size_t)3 * EMBED * EMBED];    // half(w_in)
__device__ __half g_hwo[(size_t)EMBED * EMBED];        // half(w_out)

// ---------------------------------------------------------------------------
// helpers
// ---------------------------------------------------------------------------
__device__ __forceinline__ uint32_t smem_to_u32(const void* p) {
    uint32_t a;
    asm("{ .reg .u64 t; cvta.to.shared.u64 t, %1; cvt.u32.u64 %0, t; }" : "=r"(a) : "l"(p));
    return a;
}
__device__ __forceinline__ uint32_t h2u(__half2 h) { return *reinterpret_cast<uint32_t*>(&h); }

__device__ __forceinline__ void mma_f16(float* c, const uint32_t* a, const uint32_t* b) {
    asm volatile(
        "mma.sync.aligned.m16n8k16.row.col.f32.f16.f16.f32 "
        "{%0,%1,%2,%3}, {%4,%5,%6,%7}, {%8,%9}, {%0,%1,%2,%3};\n"
        : "+f"(c[0]), "+f"(c[1]), "+f"(c[2]), "+f"(c[3])
        : "r"(a[0]), "r"(a[1]), "r"(a[2]), "r"(a[3]), "r"(b[0]), "r"(b[1]));
}
__device__ __forceinline__ void ldm_x4(uint32_t* r, uint32_t addr) {
    asm volatile("ldmatrix.sync.aligned.m8n8.x4.shared.b16 {%0,%1,%2,%3}, [%4];"
        : "=r"(r[0]), "=r"(r[1]), "=r"(r[2]), "=r"(r[3]) : "r"(addr));
}
__device__ __forceinline__ void ldm_x4_trans(uint32_t* r, uint32_t addr) {
    asm volatile("ldmatrix.sync.aligned.m8n8.x4.trans.shared.b16 {%0,%1,%2,%3}, [%4];"
        : "=r"(r[0]), "=r"(r[1]), "=r"(r[2]), "=r"(r[3]) : "r"(addr));
}
__device__ __forceinline__ float sigm(float x) {
    float e = __expf(-x);
    return __fdividef(1.0f, 1.0f + e);
}
#define CP_ASYNC16(dst, src) \
    asm volatile("cp.async.ca.shared.global [%0], [%1], 16;" :: "r"((uint32_t)(dst)), "l"(src))
#define CP_COMMIT() asm volatile("cp.async.commit_group;" ::: "memory")
#define CP_WAIT(n)  asm volatile("cp.async.wait_group %0;" :: "n"(n) : "memory")

// ---------------------------------------------------------------------------
// fp32 -> fp16 converts
// ---------------------------------------------------------------------------
__global__ void f2h3_kernel(const float* __restrict__ a, const float* __restrict__ b,
                            const float* __restrict__ c, __half* __restrict__ out, int n4) {
    int i = blockIdx.x * blockDim.x + threadIdx.x;
    const float* src = (blockIdx.z == 0) ? a : (blockIdx.z == 1) ? b : c;
    if (i < n4) {
        float4 v = ((const float4*)src)[i];
        ((uint2*)out)[(size_t)blockIdx.z * n4 + i] =
            make_uint2(h2u(__floats2half2_rn(v.x, v.y)), h2u(__floats2half2_rn(v.z, v.w)));
    }
}
__global__ void f2h_kernel(const float* __restrict__ in, __half* __restrict__ out, int n4) {
    int i = blockIdx.x * blockDim.x + threadIdx.x;
    if (i < n4) {
        float4 v = ((const float4*)in)[i];
        ((uint2*)out)[i] = make_uint2(h2u(__floats2half2_rn(v.x, v.y)),
                                      h2u(__floats2half2_rn(v.z, v.w)));
    }
}

// ---------------------------------------------------------------------------
// NT GEMM, all-half, fp16 MMA fp32 accum, cp.async 2-stage double buffer,
// BK=64. Block tile 128x128, FOUR warps (128 threads), warp tile 64x64 (2x2)
// -> 1.5x fewer LDSM wavefronts per FLOP than 64x32.
// grid.z batches independent GEMMs. OH: output half.
// dyn smem: 2 stages x 2 ops x 128 x 72 halves = 73728 B (2 CTA/SM)
// ---------------------------------------------------------------------------
#define GLDH 72
#define GASZ (128 * GLDH * 2)          // 18432 B per operand per stage
#define GEMM_SMEM (4 * GASZ)           // 73728

template<int OH>
__global__ void __launch_bounds__(128, 2) gemm_h_kernel(
    const __half* __restrict__ Xb, const __half* __restrict__ Wb,
    const float* __restrict__ biasb,
    void* __restrict__ C0, void* __restrict__ C1, void* __restrict__ C2,
    int K, int N, long xs, long ws, long bs)
{
    extern __shared__ char smraw[];
    const uint32_t smb = smem_to_u32(smraw);
    // layout: A[s0], A[s1], B[s0], B[s1]
    const uint32_t aB[2] = { smb, smb + GASZ };
    const uint32_t bB[2] = { smb + 2 * GASZ, smb + 3 * GASZ };

    const int z = blockIdx.z;
    const __half* X = Xb + (size_t)z * xs;
    const __half* W = Wb + (size_t)z * ws;
    const float* bias = biasb + (size_t)z * bs;
    void* Cv = (z == 0) ? C0 : (z == 1) ? C1 : C2;

    const int tid = threadIdx.x;
    const int lane = tid & 31, wid = tid >> 5;
    const int g = lane >> 2, tig = lane & 3;
    const int warp_m = wid >> 1, warp_n = wid & 1;   // 2 x 2
    const int m0 = blockIdx.y * 128, n0 = blockIdx.x * 128;

    float acc[4][8][4];
#pragma unroll
    for (int i = 0; i < 4; i++)
#pragma unroll
        for (int j = 0; j < 8; j++)
#pragma unroll
            for (int r = 0; r < 4; r++) acc[i][j][r] = 0.f;

    // staging: per operand per stage 128 rows x 8 x 16B units = 1024 units,
    // 128 threads -> 8 units per thread per operand
    int srow[8], sseg[8];
#pragma unroll
    for (int i = 0; i < 8; i++) {
        int idx = tid + i * 128;
        srow[i] = idx >> 3;
        sseg[i] = (idx & 7) * 8;   // halves
    }

    // ldmatrix lane offsets (halves)
    uint32_t a_off[4], b_off[4];
#pragma unroll
    for (int i = 0; i < 4; i++)
        a_off[i] = (uint32_t)((warp_m * 64 + i * 16 + (lane & 15)) * GLDH + (lane >> 4) * 8);
#pragma unroll
    for (int jp = 0; jp < 4; jp++)
        b_off[jp] = (uint32_t)((warp_n * 64 + jp * 16 + (lane >> 4) * 8 + (lane & 7)) * GLDH
                               + ((lane >> 3) & 1) * 8);

    const int nk = K / 64;   // 16

    auto stage = [&](int chunk, int s) {
        const int k0 = chunk * 64;
#pragma unroll
        for (int i = 0; i < 8; i++) {
            CP_ASYNC16(aB[s] + (uint32_t)(srow[i] * GLDH + sseg[i]) * 2,
                       &X[(size_t)(m0 + srow[i]) * K + k0 + sseg[i]]);
            CP_ASYNC16(bB[s] + (uint32_t)(srow[i] * GLDH + sseg[i]) * 2,
                       &W[(size_t)(n0 + srow[i]) * K + k0 + sseg[i]]);
        }
    };

    // prologue
    stage(0, 0); CP_COMMIT();

    for (int kc = 0; kc < nk; kc++) {
        const int buf = kc & 1;
        if (kc + 1 < nk) {
            stage(kc + 1, buf ^ 1);
            CP_COMMIT();
            CP_WAIT(1);
        } else {
            CP_WAIT(0);
        }
        __syncthreads();

#pragma unroll
        for (int kk = 0; kk < 4; kk++) {
            const uint32_t kb = kk * 16;
            uint32_t af[4][4], bf[8][2];
#pragma unroll
            for (int i = 0; i < 4; i++)
                ldm_x4(af[i], aB[buf] + (a_off[i] + kb) * 2);
#pragma unroll
            for (int jp = 0; jp < 4; jp++) {
                uint32_t t[4];
                ldm_x4(t, bB[buf] + (b_off[jp] + kb) * 2);
                bf[jp * 2][0] = t[0]; bf[jp * 2][1] = t[1];
                bf[jp * 2 + 1][0] = t[2]; bf[jp * 2 + 1][1] = t[3];
            }
#pragma unroll
            for (int i = 0; i < 4; i++)
#pragma unroll
                for (int j = 0; j < 8; j++) mma_f16(acc[i][j], af[i], bf[j]);
        }
        __syncthreads();   // all warps done with buf before it is overwritten
    }

    // Epilogue + bias
#pragma unroll
    for (int i = 0; i < 4; i++) {
#pragma unroll
        for (int j = 0; j < 8; j++) {
            int m = m0 + warp_m * 64 + i * 16 + g;
            int n = n0 + warp_n * 64 + j * 8 + 2 * tig;
            float b0v = bias[n], b1v = bias[n + 1];
            float c0 = acc[i][j][0] + b0v, c1 = acc[i][j][1] + b1v;
            float c2 = acc[i][j][2] + b0v, c3 = acc[i][j][3] + b1v;
            if (OH) {
                __half* C = (__half*)Cv;
                *(__half2*)&C[(size_t)m * N + n] = __floats2half2_rn(c0, c1);
                *(__half2*)&C[(size_t)(m + 8) * N + n] = __floats2half2_rn(c2, c3);
            } else {
                float* C = (float*)Cv;
                *(float2*)&C[(size_t)m * N + n] = make_float2(c0, c1);
                *(float2*)&C[(size_t)(m + 8) * N + n] = make_float2(c2, c3);
            }
        }
    }
}

// ---------------------------------------------------------------------------
// Flash-style fp16 sigmoid attention, cp.async double-buffered K/V
// (PROVEN R8/R13 version, unchanged).
// grid (8, 64): 128 t-rows/CTA, 8 warps, warp tile 16t x 64s x 64d.
// dyn smem: K/V 2 bufs x 2 arrays x 64 x 72 halves (36864B)
//         + S stage 8 x 16 x 72 floats (36864B) = 73728 B
// ---------------------------------------------------------------------------
#define ALD 72
#define SLD 72
#define ATTN_SMEM (2 * 2 * 64 * ALD * 2 + 8 * 16 * SLD * 4)

__global__ void __launch_bounds__(256, 2) attn_h_kernel(
    const __half* __restrict__ q, const __half* __restrict__ k,
    const __half* __restrict__ v, __half* __restrict__ o,
    float* __restrict__ attn)
{
    extern __shared__ char smraw[];
    __half* KV = (__half*)smraw;                       // [2][2][64][ALD] (buf, K/V)
    float*  Sst = (float*)(KV + 2 * 2 * 64 * ALD);     // [8][16][SLD]

    const int tid = threadIdx.x;
    const int lane = tid & 31, wid = tid >> 5;
    const int g = lane >> 2, tig = lane & 3;
    const int t0 = blockIdx.x * 128;
    const int bh = blockIdx.y;
    const int b = bh >> 4, h = bh & 15;
    const size_t hoff = (size_t)h * HDIM;
    const int tw = t0 + wid * 16;

    const uint32_t kv_base = smem_to_u32(KV);
    const uint32_t bufsz = 2 * 64 * ALD * 2;
    const uint32_t vofs = 64 * ALD * 2;
    float* sw = Sst + wid * 16 * SLD;

    uint32_t k_off[4];
#pragma unroll
    for (int jp = 0; jp < 4; jp++)
        k_off[jp] = (uint32_t)((jp * 16 + (lane >> 4) * 8 + (lane & 7)) * ALD
                               + ((lane >> 3) & 1) * 8);
    const int tsel = lane >> 3, vr_ = lane & 7;

    const int srow = tid >> 2, ssg = (tid & 3) * 16;    // halves

    const __half2 hs = __floats2half2_rn(SCALE, SCALE);
    uint32_t qf[4][4];
#pragma unroll
    for (int kt = 0; kt < 4; kt++) {
        size_t r0 = ((size_t)(tw + g) * BSZ + b) * EMBED + hoff + kt * 16 + 2 * tig;
        size_t r1 = ((size_t)(tw + g + 8) * BSZ + b) * EMBED + hoff + kt * 16 + 2 * tig;
        qf[kt][0] = h2u(__hmul2(*(const __half2*)&q[r0], hs));
        qf[kt][1] = h2u(__hmul2(*(const __half2*)&q[r1], hs));
        qf[kt][2] = h2u(__hmul2(*(const __half2*)&q[r0 + 8], hs));
        qf[kt][3] = h2u(__hmul2(*(const __half2*)&q[r1 + 8], hs));
    }

    float oacc[8][4];
#pragma unroll
    for (int j = 0; j < 8; j++)
#pragma unroll
        for (int r = 0; r < 4; r++) oacc[j][r] = 0.f;

    // prologue
    {
        size_t gro = ((size_t)srow * BSZ + b) * EMBED + hoff + ssg;
        uint32_t db = kv_base + (uint32_t)(srow * ALD + ssg) * 2;
        CP_ASYNC16(db, &k[gro]);
        CP_ASYNC16(db + 16, &k[gro + 8]);
        CP_ASYNC16(db + vofs, &v[gro]);
        CP_ASYNC16(db + vofs + 16, &v[gro + 8]);
        CP_COMMIT();
    }

    for (int ci = 0; ci < 16; ci++) {
        const int s0 = ci * 64;
        const int buf = ci & 1;
        const uint32_t kbB = kv_base + buf * bufsz;
        const uint32_t vbB = kbB + vofs;

        if (ci < 15) {
            size_t gro = ((size_t)(s0 + 64 + srow) * BSZ + b) * EMBED + hoff + ssg;
            uint32_t db = kv_base + (buf ^ 1) * bufsz + (uint32_t)(srow * ALD + ssg) * 2;
            CP_ASYNC16(db, &k[gro]);
            CP_ASYNC16(db + 16, &k[gro + 8]);
            CP_ASYNC16(db + vofs, &v[gro]);
            CP_ASYNC16(db + vofs + 16, &v[gro + 8]);
            CP_COMMIT();
            CP_WAIT(1);
        } else {
            CP_WAIT(0);
        }
        __syncthreads();

        // ---- S = Q K^T ----
        float sacc[8][4];
#pragma unroll
        for (int j = 0; j < 8; j++)
#pragma unroll
            for (int r = 0; r < 4; r++) sacc[j][r] = 0.f;

#pragma unroll
        for (int kt = 0; kt < 4; kt++) {
            uint32_t kb[8][2];
#pragma unroll
            for (int jp = 0; jp < 4; jp++) {
                uint32_t t[4];
                ldm_x4(t, kbB + (k_off[jp] + kt * 16) * 2);
                kb[jp * 2][0] = t[0]; kb[jp * 2][1] = t[1];
                kb[jp * 2 + 1][0] = t[2]; kb[jp * 2 + 1][1] = t[3];
            }
#pragma unroll
            for (int j = 0; j < 8; j++) mma_f16(sacc[j], qf[kt], kb[j]);
        }

        // ---- sigmoid -> per-warp smem stage + half2 pack ----
        uint32_t sf[8][2];
#pragma unroll
        for (int j = 0; j < 8; j++) {
            float v0 = sigm(sacc[j][0]), v1 = sigm(sacc[j][1]);
            float v2 = sigm(sacc[j][2]), v3 = sigm(sacc[j][3]);
            *(float2*)&sw[g * SLD + j * 8 + 2 * tig] = make_float2(v0, v1);
            *(float2*)&sw[(g + 8) * SLD + j * 8 + 2 * tig] = make_float2(v2, v3);
            sf[j][0] = h2u(__floats2half2_rn(v0, v1));
            sf[j][1] = h2u(__floats2half2_rn(v2, v3));
        }
        __syncwarp();

        // ---- coalesced attn store: 16 rows x 256B, STG.128 ----
        {
            size_t abase = ((size_t)bh * TLEN + tw) * TLEN + s0;
#pragma unroll
            for (int it = 0; it < 8; it++) {
                int row = it * 2 + (lane >> 4);
                int col = (lane & 15) * 4;
                float4 val = *(float4*)&sw[row * SLD + col];
                __stcs((float4*)&attn[abase + (size_t)row * TLEN + col], val);
            }
        }

        // ---- O += S * V ----
#pragma unroll
        for (int kt = 0; kt < 4; kt++) {
            uint32_t af[4] = { sf[2 * kt][0], sf[2 * kt][1], sf[2 * kt + 1][0], sf[2 * kt + 1][1] };
#pragma unroll
            for (int db = 0; db < 4; db++) {
                int sr = kt * 16 + (tsel & 1) * 8 + vr_;
                int dc = db * 16 + (tsel >> 1) * 8;
                uint32_t addr = vbB + (uint32_t)(sr * ALD + dc) * 2;
                uint32_t vr[4];
                ldm_x4_trans(vr, addr);
                mma_f16(oacc[2 * db], af, vr);
                mma_f16(oacc[2 * db + 1], af, vr + 2);
            }
        }
        __syncthreads();   // all warps done with buf before overwrite
    }

    // Write O (half)
#pragma unroll
    for (int j = 0; j < 8; j++) {
        size_t r0 = ((size_t)(tw + g) * BSZ + b) * EMBED + hoff + j * 8 + 2 * tig;
        size_t r1 = ((size_t)(tw + g + 8) * BSZ + b) * EMBED + hoff + j * 8 + 2 * tig;
        *(__half2*)&o[r0] = __floats2half2_rn(oacc[j][0], oacc[j][1]);
        *(__half2*)&o[r1] = __floats2half2_rn(oacc[j][2], oacc[j][3]);
    }
}

// ---------------------------------------------------------------------------
// Launch
// ---------------------------------------------------------------------------
extern "C" void kernel_launch(void* const* d_in, const int* in_sizes, int n_in,
                              void* d_out, int out_size)
{
    const float* query = (const float*)d_in[0];
    const float* keyt  = (const float*)d_in[1];
    const float* value = (const float*)d_in[2];
    const float* w_in  = (const float*)d_in[3];   // [3E, E]
    const float* b_in  = (const float*)d_in[4];   // [3E]
    const float* w_out = (const float*)d_in[5];   // [E, E]
    const float* b_out = (const float*)d_in[6];   // [E]

    float* out  = (float*)d_out;                               // attn_output [T,B,E]
    float* attn = out + (size_t)TLEN * BSZ * EMBED;            // attn [B*H,T,T]

    __half *q, *k, *v, *o, *hx, *hwi, *hwo;
    cudaGetSymbolAddress((void**)&q, g_q);
    cudaGetSymbolAddress((void**)&k, g_k);
    cudaGetSymbolAddress((void**)&v, g_v);
    cudaGetSymbolAddress((void**)&o, g_o);
    cudaGetSymbolAddress((void**)&hx, g_hx);
    cudaGetSymbolAddress((void**)&hwi, g_hwi);
    cudaGetSymbolAddress((void**)&hwo, g_hwo);

    cudaFuncSetAttribute(gemm_h_kernel<1>, cudaFuncAttributeMaxDynamicSharedMemorySize, GEMM_SMEM);
    cudaFuncSetAttribute(gemm_h_kernel<0>, cudaFuncAttributeMaxDynamicSharedMemorySize, GEMM_SMEM);
    cudaFuncSetAttribute(attn_h_kernel, cudaFuncAttributeMaxDynamicSharedMemorySize, ATTN_SMEM);

    const size_t NE = (size_t)MROWS * EMBED;       // 4M
    const size_t WE = (size_t)EMBED * EMBED;       // 1M

    // fp32 -> fp16 converts
    f2h3_kernel<<<dim3((int)(NE / 4 + 255) / 256, 1, 3), 256>>>(query, keyt, value, hx, (int)(NE / 4));
    f2h_kernel<<<(int)(3 * WE / 4 + 255) / 256, 256>>>(w_in, hwi, (int)(3 * WE / 4));
    f2h_kernel<<<(int)(WE / 4 + 255) / 256, 256>>>(w_out, hwo, (int)(WE / 4));

    // QKV projections: one batched launch, grid.z = 3, 128 threads/CTA
    gemm_h_kernel<1><<<dim3(EMBED / 128, MROWS / 128, 3), 128, GEMM_SMEM>>>(
        hx, hwi, b_in, q, k, v, EMBED, EMBED, (long)NE, (long)WE, (long)EMBED);

    // Fused attention
    attn_h_kernel<<<dim3(TLEN / 128, BSZ * NHEAD), 256, ATTN_SMEM>>>(q, k, v, o, attn);

    // Output projection (half in, float out)
    gemm_h_kernel<0><<<dim3(EMBED / 128, MROWS / 128, 1), 128, GEMM_SMEM>>>(
        o, hwo, b_out, out, out, out, EMBED, EMBED, 0, 0, 0);
}

// round 15
// speedup vs baseline: 1.0376x; 1.0376x over previous
#include <cuda_runtime.h>
#include <cuda_fp16.h>
#include <cstdint>

#define EMBED 1024
#define NHEAD 16
#define HDIM  64
#define TLEN  1024
#define BSZ   4
#define MROWS (TLEN*BSZ)          // 4096
#define SCALE 0.03125f            // 1/sqrt(1024)

// Scratch (device globals; no allocation allowed)
__device__ __half g_q[(size_t)MROWS * EMBED];
__device__ __half g_k[(size_t)MROWS * EMBED];
__device__ __half g_v[(size_t)MROWS * EMBED];
__device__ __half g_o[(size_t)MROWS * EMBED];
__device__ __half g_hx[(size_t)3 * MROWS * EMBED];     // half(query|key|value)
__device__ __half g_hwi[(size_t)3 * EMBED * EMBED];    // half(w_in)
__device__ __half g_hwo[(size_t)EMBED * EMBED];        // half(w_out)

// ---------------------------------------------------------------------------
// helpers
// ---------------------------------------------------------------------------
__device__ __forceinline__ uint32_t smem_to_u32(const void* p) {
    uint32_t a;
    asm("{ .reg .u64 t; cvta.to.shared.u64 t, %1; cvt.u32.u64 %0, t; }" : "=r"(a) : "l"(p));
    return a;
}
__device__ __forceinline__ uint32_t h2u(__half2 h) { return *reinterpret_cast<uint32_t*>(&h); }

__device__ __forceinline__ void mma_f16(float* c, const uint32_t* a, const uint32_t* b) {
    asm volatile(
        "mma.sync.aligned.m16n8k16.row.col.f32.f16.f16.f32 "
        "{%0,%1,%2,%3}, {%4,%5,%6,%7}, {%8,%9}, {%0,%1,%2,%3};\n"
        : "+f"(c[0]), "+f"(c[1]), "+f"(c[2]), "+f"(c[3])
        : "r"(a[0]), "r"(a[1]), "r"(a[2]), "r"(a[3]), "r"(b[0]), "r"(b[1]));
}
__device__ __forceinline__ void ldm_x4(uint32_t* r, uint32_t addr) {
    asm volatile("ldmatrix.sync.aligned.m8n8.x4.shared.b16 {%0,%1,%2,%3}, [%4];"
        : "=r"(r[0]), "=r"(r[1]), "=r"(r[2]), "=r"(r[3]) : "r"(addr));
}
__device__ __forceinline__ void ldm_x4_trans(uint32_t* r, uint32_t addr) {
    asm volatile("ldmatrix.sync.aligned.m8n8.x4.trans.shared.b16 {%0,%1,%2,%3}, [%4];"
        : "=r"(r[0]), "=r"(r[1]), "=r"(r[2]), "=r"(r[3]) : "r"(addr));
}
__device__ __forceinline__ float sigm(float x) {
    float e = __expf(-x);
    return __fdividef(1.0f, 1.0f + e);
}
#define CP_ASYNC16(dst, src) \
    asm volatile("cp.async.ca.shared.global [%0], [%1], 16;" :: "r"((uint32_t)(dst)), "l"(src))
#define CP_COMMIT() asm volatile("cp.async.commit_group;" ::: "memory")
#define CP_WAIT(n)  asm volatile("cp.async.wait_group %0;" :: "n"(n) : "memory")

// ---------------------------------------------------------------------------
// fp32 -> fp16 converts
// ---------------------------------------------------------------------------
__global__ void f2h3_kernel(const float* __restrict__ a, const float* __restrict__ b,
                            const float* __restrict__ c, __half* __restrict__ out, int n4) {
    int i = blockIdx.x * blockDim.x + threadIdx.x;
    const float* src = (blockIdx.z == 0) ? a : (blockIdx.z == 1) ? b : c;
    if (i < n4) {
        float4 v = ((const float4*)src)[i];
        ((uint2*)out)[(size_t)blockIdx.z * n4 + i] =
            make_uint2(h2u(__floats2half2_rn(v.x, v.y)), h2u(__floats2half2_rn(v.z, v.w)));
    }
}
__global__ void f2h_kernel(const float* __restrict__ in, __half* __restrict__ out, int n4) {
    int i = blockIdx.x * blockDim.x + threadIdx.x;
    if (i < n4) {
        float4 v = ((const float4*)in)[i];
        ((uint2*)out)[i] = make_uint2(h2u(__floats2half2_rn(v.x, v.y)),
                                      h2u(__floats2half2_rn(v.z, v.w)));
    }
}

// ---------------------------------------------------------------------------
// NT GEMM (PROVEN R13): all-half, fp16 MMA fp32 accum, cp.async 2-stage
// double buffer, BK=64. Block 128x128, 8 warps (2x4), warp tile 64x32.
// grid.z batches independent GEMMs. OH: output half.
// dyn smem: 2 stages x 2 ops x 128 x 72 halves = 73728 B (2 CTA/SM)
// ---------------------------------------------------------------------------
#define GLDH 72
#define GASZ (128 * GLDH * 2)          // 18432 B per operand per stage
#define GEMM_SMEM (4 * GASZ)           // 73728

template<int OH>
__global__ void __launch_bounds__(256, 2) gemm_h_kernel(
    const __half* __restrict__ Xb, const __half* __restrict__ Wb,
    const float* __restrict__ biasb,
    void* __restrict__ C0, void* __restrict__ C1, void* __restrict__ C2,
    int K, int N, long xs, long ws, long bs)
{
    extern __shared__ char smraw[];
    const uint32_t smb = smem_to_u32(smraw);
    const uint32_t aB[2] = { smb, smb + GASZ };
    const uint32_t bB[2] = { smb + 2 * GASZ, smb + 3 * GASZ };

    const int z = blockIdx.z;
    const __half* X = Xb + (size_t)z * xs;
    const __half* W = Wb + (size_t)z * ws;
    const float* bias = biasb + (size_t)z * bs;
    void* Cv = (z == 0) ? C0 : (z == 1) ? C1 : C2;

    const int tid = threadIdx.x;
    const int lane = tid & 31, wid = tid >> 5;
    const int g = lane >> 2, tig = lane & 3;
    const int warp_m = wid >> 2, warp_n = wid & 3;   // 2 x 4
    const int m0 = blockIdx.y * 128, n0 = blockIdx.x * 128;

    float acc[4][4][4];
#pragma unroll
    for (int i = 0; i < 4; i++)
#pragma unroll
        for (int j = 0; j < 4; j++)
#pragma unroll
            for (int r = 0; r < 4; r++) acc[i][j][r] = 0.f;

    int srow[4], sseg[4];
#pragma unroll
    for (int i = 0; i < 4; i++) {
        int idx = tid + i * 256;
        srow[i] = idx >> 3;
        sseg[i] = (idx & 7) * 8;   // halves
    }

    uint32_t a_off[4], b_off[2];
#pragma unroll
    for (int i = 0; i < 4; i++)
        a_off[i] = (uint32_t)((warp_m * 64 + i * 16 + (lane & 15)) * GLDH + (lane >> 4) * 8);
#pragma unroll
    for (int jp = 0; jp < 2; jp++)
        b_off[jp] = (uint32_t)((warp_n * 32 + jp * 16 + (lane >> 4) * 8 + (lane & 7)) * GLDH
                               + ((lane >> 3) & 1) * 8);

    const int nk = K / 64;   // 16

    auto stage = [&](int chunk, int s) {
        const int k0 = chunk * 64;
#pragma unroll
        for (int i = 0; i < 4; i++) {
            CP_ASYNC16(aB[s] + (uint32_t)(srow[i] * GLDH + sseg[i]) * 2,
                       &X[(size_t)(m0 + srow[i]) * K + k0 + sseg[i]]);
            CP_ASYNC16(bB[s] + (uint32_t)(srow[i] * GLDH + sseg[i]) * 2,
                       &W[(size_t)(n0 + srow[i]) * K + k0 + sseg[i]]);
        }
    };

    stage(0, 0); CP_COMMIT();

    for (int kc = 0; kc < nk; kc++) {
        const int buf = kc & 1;
        if (kc + 1 < nk) {
            stage(kc + 1, buf ^ 1);
            CP_COMMIT();
            CP_WAIT(1);
        } else {
            CP_WAIT(0);
        }
        __syncthreads();

#pragma unroll
        for (int kk = 0; kk < 4; kk++) {
            const uint32_t kb = kk * 16;
            uint32_t af[4][4], bf[4][2];
#pragma unroll
            for (int i = 0; i < 4; i++)
                ldm_x4(af[i], aB[buf] + (a_off[i] + kb) * 2);
#pragma unroll
            for (int jp = 0; jp < 2; jp++) {
                uint32_t t[4];
                ldm_x4(t, bB[buf] + (b_off[jp] + kb) * 2);
                bf[jp * 2][0] = t[0]; bf[jp * 2][1] = t[1];
                bf[jp * 2 + 1][0] = t[2]; bf[jp * 2 + 1][1] = t[3];
            }
#pragma unroll
            for (int i = 0; i < 4; i++)
#pragma unroll
                for (int j = 0; j < 4; j++) mma_f16(acc[i][j], af[i], bf[j]);
        }
        __syncthreads();
    }

    // Epilogue + bias
#pragma unroll
    for (int i = 0; i < 4; i++) {
#pragma unroll
        for (int j = 0; j < 4; j++) {
            int m = m0 + warp_m * 64 + i * 16 + g;
            int n = n0 + warp_n * 32 + j * 8 + 2 * tig;
            float b0v = bias[n], b1v = bias[n + 1];
            float c0 = acc[i][j][0] + b0v, c1 = acc[i][j][1] + b1v;
            float c2 = acc[i][j][2] + b0v, c3 = acc[i][j][3] + b1v;
            if (OH) {
                __half* C = (__half*)Cv;
                *(__half2*)&C[(size_t)m * N + n] = __floats2half2_rn(c0, c1);
                *(__half2*)&C[(size_t)(m + 8) * N + n] = __floats2half2_rn(c2, c3);
            } else {
                float* C = (float*)Cv;
                *(float2*)&C[(size_t)m * N + n] = make_float2(c0, c1);
                *(float2*)&C[(size_t)(m + 8) * N + n] = make_float2(c2, c3);
            }
        }
    }
}

// ---------------------------------------------------------------------------
// Flash-style fp16 sigmoid attention, cp.async double-buffered K/V.
// NEW: 4 warps (128 threads), warp tile 32t x 64s x 64d -> K and V fragments
// each feed TWO m-tiles (2x LDSM reuse vs 16t tile).
// grid (8, 64): 128 t-rows/CTA.
// dyn smem: K/V 2 bufs x 2 arrays x 64 x 72 halves (36864B)
//         + S stage 4 warps x 32 x 72 floats (36864B) = 73728 B (2 CTA/SM)
// ---------------------------------------------------------------------------
#define ALD 72
#define SLD 72
#define ATTN_SMEM (2 * 2 * 64 * ALD * 2 + 4 * 32 * SLD * 4)

__global__ void __launch_bounds__(128, 2) attn_h_kernel(
    const __half* __restrict__ q, const __half* __restrict__ k,
    const __half* __restrict__ v, __half* __restrict__ o,
    float* __restrict__ attn)
{
    extern __shared__ char smraw[];
    __half* KV = (__half*)smraw;                       // [2][2][64][ALD] (buf, K/V)
    float*  Sst = (float*)(KV + 2 * 2 * 64 * ALD);     // [4][32][SLD]

    const int tid = threadIdx.x;
    const int lane = tid & 31, wid = tid >> 5;         // wid 0..3
    const int g = lane >> 2, tig = lane & 3;
    const int t0 = blockIdx.x * 128;
    const int bh = blockIdx.y;
    const int b = bh >> 4, h = bh & 15;
    const size_t hoff = (size_t)h * HDIM;
    const int tw = t0 + wid * 32;                      // warp's first t-row (32 rows)

    const uint32_t kv_base = smem_to_u32(KV);
    const uint32_t bufsz = 2 * 64 * ALD * 2;
    const uint32_t vofs = 64 * ALD * 2;
    float* sw = Sst + wid * 32 * SLD;

    uint32_t k_off[4];
#pragma unroll
    for (int jp = 0; jp < 4; jp++)
        k_off[jp] = (uint32_t)((jp * 16 + (lane >> 4) * 8 + (lane & 7)) * ALD
                               + ((lane >> 3) & 1) * 8);
    const int tsel = lane >> 3, vr_ = lane & 7;

    // K/V staging: 128 threads, 2 per row; each covers 4 x 16B per array
    const int srow = tid >> 1, ssg = (tid & 1) * 32;   // halves

    // Q fragments: [kt][mi][4], scaled
    const __half2 hs = __floats2half2_rn(SCALE, SCALE);
    uint32_t qf[4][2][4];
#pragma unroll
    for (int kt = 0; kt < 4; kt++)
#pragma unroll
        for (int mi = 0; mi < 2; mi++) {
            size_t r0 = ((size_t)(tw + mi * 16 + g) * BSZ + b) * EMBED + hoff + kt * 16 + 2 * tig;
            size_t r1 = ((size_t)(tw + mi * 16 + g + 8) * BSZ + b) * EMBED + hoff + kt * 16 + 2 * tig;
            qf[kt][mi][0] = h2u(__hmul2(*(const __half2*)&q[r0], hs));
            qf[kt][mi][1] = h2u(__hmul2(*(const __half2*)&q[r1], hs));
            qf[kt][mi][2] = h2u(__hmul2(*(const __half2*)&q[r0 + 8], hs));
            qf[kt][mi][3] = h2u(__hmul2(*(const __half2*)&q[r1 + 8], hs));
        }

    float oacc[2][8][4];
#pragma unroll
    for (int mi = 0; mi < 2; mi++)
#pragma unroll
        for (int j = 0; j < 8; j++)
#pragma unroll
            for (int r = 0; r < 4; r++) oacc[mi][j][r] = 0.f;

    // prologue
    {
        size_t gro = ((size_t)srow * BSZ + b) * EMBED + hoff + ssg;
        uint32_t db = kv_base + (uint32_t)(srow * ALD + ssg) * 2;
#pragma unroll
        for (int u = 0; u < 4; u++) {
            CP_ASYNC16(db + u * 16, &k[gro + u * 8]);
            CP_ASYNC16(db + vofs + u * 16, &v[gro + u * 8]);
        }
        CP_COMMIT();
    }

    for (int ci = 0; ci < 16; ci++) {
        const int s0 = ci * 64;
        const int buf = ci & 1;
        const uint32_t kbB = kv_base + buf * bufsz;
        const uint32_t vbB = kbB + vofs;

        if (ci < 15) {
            size_t gro = ((size_t)(s0 + 64 + srow) * BSZ + b) * EMBED + hoff + ssg;
            uint32_t db = kv_base + (buf ^ 1) * bufsz + (uint32_t)(srow * ALD + ssg) * 2;
#pragma unroll
            for (int u = 0; u < 4; u++) {
                CP_ASYNC16(db + u * 16, &k[gro + u * 8]);
                CP_ASYNC16(db + vofs + u * 16, &v[gro + u * 8]);
            }
            CP_COMMIT();
            CP_WAIT(1);
        } else {
            CP_WAIT(0);
        }
        __syncthreads();

        // ---- S = Q K^T : K frags shared across both m-tiles ----
        float sacc[2][8][4];
#pragma unroll
        for (int mi = 0; mi < 2; mi++)
#pragma unroll
            for (int j = 0; j < 8; j++)
#pragma unroll
                for (int r = 0; r < 4; r++) sacc[mi][j][r] = 0.f;

#pragma unroll
        for (int kt = 0; kt < 4; kt++) {
            uint32_t kb[8][2];
#pragma unroll
            for (int jp = 0; jp < 4; jp++) {
                uint32_t t[4];
                ldm_x4(t, kbB + (k_off[jp] + kt * 16) * 2);
                kb[jp * 2][0] = t[0]; kb[jp * 2][1] = t[1];
                kb[jp * 2 + 1][0] = t[2]; kb[jp * 2 + 1][1] = t[3];
            }
#pragma unroll
            for (int mi = 0; mi < 2; mi++)
#pragma unroll
                for (int j = 0; j < 8; j++) mma_f16(sacc[mi][j], qf[kt][mi], kb[j]);
        }

        // ---- sigmoid -> per-warp smem stage + half2 pack ----
        uint32_t sf[2][8][2];
#pragma unroll
        for (int mi = 0; mi < 2; mi++)
#pragma unroll
            for (int j = 0; j < 8; j++) {
                float v0 = sigm(sacc[mi][j][0]), v1 = sigm(sacc[mi][j][1]);
                float v2 = sigm(sacc[mi][j][2]), v3 = sigm(sacc[mi][j][3]);
                *(float2*)&sw[(mi * 16 + g) * SLD + j * 8 + 2 * tig] = make_float2(v0, v1);
                *(float2*)&sw[(mi * 16 + g + 8) * SLD + j * 8 + 2 * tig] = make_float2(v2, v3);
                sf[mi][j][0] = h2u(__floats2half2_rn(v0, v1));
                sf[mi][j][1] = h2u(__floats2half2_rn(v2, v3));
            }
        __syncwarp();

        // ---- coalesced attn store: 32 rows x 256B, STG.128 ----
        {
            size_t abase = ((size_t)bh * TLEN + tw) * TLEN + s0;
#pragma unroll
            for (int it = 0; it < 16; it++) {
                int row = it * 2 + (lane >> 4);
                int col = (lane & 15) * 4;
                float4 val = *(float4*)&sw[row * SLD + col];
                __stcs((float4*)&attn[abase + (size_t)row * TLEN + col], val);
            }
        }

        // ---- O += S * V : V frags shared across both m-tiles ----
#pragma unroll
        for (int kt = 0; kt < 4; kt++) {
#pragma unroll
            for (int db = 0; db < 4; db++) {
                int sr = kt * 16 + (tsel & 1) * 8 + vr_;
                int dc = db * 16 + (tsel >> 1) * 8;
                uint32_t addr = vbB + (uint32_t)(sr * ALD + dc) * 2;
                uint32_t vr[4];
                ldm_x4_trans(vr, addr);
#pragma unroll
                for (int mi = 0; mi < 2; mi++) {
                    uint32_t af[4] = { sf[mi][2 * kt][0], sf[mi][2 * kt][1],
                                       sf[mi][2 * kt + 1][0], sf[mi][2 * kt + 1][1] };
                    mma_f16(oacc[mi][2 * db], af, vr);
                    mma_f16(oacc[mi][2 * db + 1], af, vr + 2);
                }
            }
        }
        __syncthreads();   // all warps done with buf before overwrite
    }

    // Write O (half)
#pragma unroll
    for (int mi = 0; mi < 2; mi++)
#pragma unroll
        for (int j = 0; j < 8; j++) {
            size_t r0 = ((size_t)(tw + mi * 16 + g) * BSZ + b) * EMBED + hoff + j * 8 + 2 * tig;
            size_t r1 = ((size_t)(tw + mi * 16 + g + 8) * BSZ + b) * EMBED + hoff + j * 8 + 2 * tig;
            *(__half2*)&o[r0] = __floats2half2_rn(oacc[mi][j][0], oacc[mi][j][1]);
            *(__half2*)&o[r1] = __floats2half2_rn(oacc[mi][j][2], oacc[mi][j][3]);
        }
}

// ---------------------------------------------------------------------------
// Launch
// ---------------------------------------------------------------------------
extern "C" void kernel_launch(void* const* d_in, const int* in_sizes, int n_in,
                              void* d_out, int out_size)
{
    const float* query = (const float*)d_in[0];
    const float* keyt  = (const float*)d_in[1];
    const float* value = (const float*)d_in[2];
    const float* w_in  = (const float*)d_in[3];   // [3E, E]
    const float* b_in  = (const float*)d_in[4];   // [3E]
    const float* w_out = (const float*)d_in[5];   // [E, E]
    const float* b_out = (const float*)d_in[6];   // [E]

    float* out  = (float*)d_out;                               // attn_output [T,B,E]
    float* attn = out + (size_t)TLEN * BSZ * EMBED;            // attn [B*H,T,T]

    __half *q, *k, *v, *o, *hx, *hwi, *hwo;
    cudaGetSymbolAddress((void**)&q, g_q);
    cudaGetSymbolAddress((void**)&k, g_k);
    cudaGetSymbolAddress((void**)&v, g_v);
    cudaGetSymbolAddress((void**)&o, g_o);
    cudaGetSymbolAddress((void**)&hx, g_hx);
    cudaGetSymbolAddress((void**)&hwi, g_hwi);
    cudaGetSymbolAddress((void**)&hwo, g_hwo);

    cudaFuncSetAttribute(gemm_h_kernel<1>, cudaFuncAttributeMaxDynamicSharedMemorySize, GEMM_SMEM);
    cudaFuncSetAttribute(gemm_h_kernel<0>, cudaFuncAttributeMaxDynamicSharedMemorySize, GEMM_SMEM);
    cudaFuncSetAttribute(attn_h_kernel, cudaFuncAttributeMaxDynamicSharedMemorySize, ATTN_SMEM);

    const size_t NE = (size_t)MROWS * EMBED;       // 4M
    const size_t WE = (size_t)EMBED * EMBED;       // 1M

    // fp32 -> fp16 converts
    f2h3_kernel<<<dim3((int)(NE / 4 + 255) / 256, 1, 3), 256>>>(query, keyt, value, hx, (int)(NE / 4));
    f2h_kernel<<<(int)(3 * WE / 4 + 255) / 256, 256>>>(w_in, hwi, (int)(3 * WE / 4));
    f2h_kernel<<<(int)(WE / 4 + 255) / 256, 256>>>(w_out, hwo, (int)(WE / 4));

    // QKV projections: one batched launch, grid.z = 3
    gemm_h_kernel<1><<<dim3(EMBED / 128, MROWS / 128, 3), 256, GEMM_SMEM>>>(
        hx, hwi, b_in, q, k, v, EMBED, EMBED, (long)NE, (long)WE, (long)EMBED);

    // Fused attention (128 threads, 4 warps of 32t x 64s)
    attn_h_kernel<<<dim3(TLEN / 128, BSZ * NHEAD), 128, ATTN_SMEM>>>(q, k, v, o, attn);

    // Output projection (half in, float out)
    gemm_h_kernel<0><<<dim3(EMBED / 128, MROWS / 128, 1), 256, GEMM_SMEM>>>(
        o, hwo, b_out, out, out, out, EMBED, EMBED, 0, 0, 0);
}